// round 6
// baseline (speedup 1.0000x reference)
#include <cuda_runtime.h>
#include <cuda_fp16.h>
#include <cstdint>

#define DD 32
#define NB 25088           // padded node capacity (N=25000)
#define MAXE 400000

// ---------------- device scratch ----------------
__device__ int   g_hist[NB];
__device__ int   g_off[NB + 1];
__device__ int   g_cur[NB];
__device__ int2  g_sorted[MAXE];          // (edge id, dst)
__device__ __half g_Z[(size_t)NB * 1024]; // Z[n][h*32+k] fp16, 51.4 MB
__device__ uint2 g_B1[2 * 128 * 32];      // B fragments for zgemm

__device__ __forceinline__ uint32_t h2pack(float lo, float hi) {
    uint32_t r;
    asm("cvt.rn.f16x2.f32 %0, %1, %2;" : "=r"(r) : "f"(hi), "f"(lo));
    return r;
}
__device__ __forceinline__ void mma16816(float c[4], uint32_t a0, uint32_t a1,
                                         uint32_t a2, uint32_t a3,
                                         uint32_t b0, uint32_t b1) {
    asm volatile(
        "mma.sync.aligned.m16n8k16.row.col.f32.f16.f16.f32 "
        "{%0,%1,%2,%3}, {%4,%5,%6,%7}, {%8,%9}, {%0,%1,%2,%3};"
        : "+f"(c[0]), "+f"(c[1]), "+f"(c[2]), "+f"(c[3])
        : "r"(a0), "r"(a1), "r"(a2), "r"(a3), "r"(b0), "r"(b1));
}
__device__ __forceinline__ void red_add_f32(float* p, float v) {
    asm volatile("red.global.add.f32 [%0], %1;" :: "l"(p), "f"(v) : "memory");
}

// ---------------- sort kernels ----------------
__global__ void zero_hist() {
    int i = blockIdx.x * blockDim.x + threadIdx.x;
    if (i < NB) g_hist[i] = 0;
}
__global__ void count_kernel(const int* __restrict__ src, int E) {
    int e = blockIdx.x * blockDim.x + threadIdx.x;
    if (e < E) atomicAdd(&g_hist[src[e]], 1);
}
__global__ void scan_kernel() {
    __shared__ int ssum[1024];
    const int t = threadIdx.x;
    const int base = t * 25;  // 1024*25 = 25600 >= NB
    int s = 0;
#pragma unroll 5
    for (int j = 0; j < 25; ++j) {
        int idx = base + j;
        if (idx < NB) s += g_hist[idx];
    }
    ssum[t] = s;
    __syncthreads();
    for (int off = 1; off < 1024; off <<= 1) {
        int v = (t >= off) ? ssum[t - off] : 0;
        __syncthreads();
        ssum[t] += v;
        __syncthreads();
    }
    int run = (t > 0) ? ssum[t - 1] : 0;
    for (int j = 0; j < 25; ++j) {
        int idx = base + j;
        if (idx < NB) {
            g_off[idx] = run;
            g_cur[idx] = run;
            run += g_hist[idx];
        }
    }
    if (t == 1023) g_off[NB] = run;
}
__global__ void scatter_kernel(const int* __restrict__ src,
                               const int* __restrict__ dst, int E) {
    int e = blockIdx.x * blockDim.x + threadIdx.x;
    if (e < E) {
        int pos = atomicAdd(&g_cur[src[e]], 1);
        g_sorted[pos] = make_int2(e, dst[e]);
    }
}

// ---------------- B fragments for zgemm ----------------
// B1[d][j] = edge_W[(d*32 + (j>>5))*32 + (j&31)],  j = h*32+k  (n-dim of GEMM)
__global__ void prep_B1(const float* __restrict__ eW) {
    int idx = blockIdx.x * blockDim.x + threadIdx.x;  // 0..8191
    if (idx >= 2 * 128 * 32) return;
    int lane = idx & 31, nt = (idx >> 5) & 127, ks = idx >> 12;
    int g = lane >> 2, tig = lane & 3;
    int j = nt * 8 + g;
    int h = j >> 5, k = j & 31;
    auto B = [&](int d) { return eW[(d * 32 + h) * 32 + k]; };
    int d0 = ks * 16;
    uint2 r;
    r.x = h2pack(B(d0 + 2 * tig),     B(d0 + 2 * tig + 1));
    r.y = h2pack(B(d0 + 2 * tig + 8), B(d0 + 2 * tig + 9));
    g_B1[idx] = r;
}

// ---------------- Z GEMM: Z[n, h*32+k] = sum_d x[n,d] * B1[d][h*32+k] ----------------
#define ZG_SMEM (65536 + 8192)
__global__ void __launch_bounds__(256)
zgemm_kernel(const float* __restrict__ x, int N, int MT) {
    extern __shared__ char smem[];
    uint2* sB = (uint2*)smem;                       // 8192 uint2 = 64KB
    uint32_t* sx = (uint32_t*)(smem + 65536);       // 8 warps x [16 rows][16 u32]

    const int t = threadIdx.x, lane = t & 31, w = t >> 5;
    const int g = lane >> 2, tig = lane & 3;

    {   // load B fragments to smem
        const uint4* gb = (const uint4*)g_B1;
        uint4* sb4 = (uint4*)smem;
#pragma unroll
        for (int i = 0; i < 16; ++i) sb4[t + i * 256] = gb[t + i * 256];
    }
    __syncthreads();

    int mtile = blockIdx.x * 8 + w;
    if (mtile >= MT) return;
    int n0 = mtile * 16;

    uint32_t* sxw = sx + w * 256;  // [16][16]
    if (lane < 16) {
        int n = n0 + lane;
        if (n >= N) n = 0;
        const float4* xp = (const float4*)(x + (size_t)n * 32);
#pragma unroll
        for (int j = 0; j < 8; ++j) {
            float4 v = xp[j];
            sxw[lane * 16 + 2 * j + 0] = h2pack(v.x, v.y);
            sxw[lane * 16 + 2 * j + 1] = h2pack(v.z, v.w);
        }
    }
    __syncwarp();

    uint32_t A[2][4];
#pragma unroll
    for (int ks = 0; ks < 2; ++ks) {
        A[ks][0] = sxw[g * 16 + ks * 8 + tig];
        A[ks][1] = sxw[(g + 8) * 16 + ks * 8 + tig];
        A[ks][2] = sxw[g * 16 + ks * 8 + tig + 4];
        A[ks][3] = sxw[(g + 8) * 16 + ks * 8 + tig + 4];
    }

    uint32_t* Zlo = ((uint32_t*)g_Z) + (size_t)(n0 + g) * 512 + tig;
    uint32_t* Zhi = ((uint32_t*)g_Z) + (size_t)(n0 + g + 8) * 512 + tig;

#pragma unroll 4
    for (int nt = 0; nt < 128; ++nt) {
        float c[4] = {0.f, 0.f, 0.f, 0.f};
#pragma unroll
        for (int ks = 0; ks < 2; ++ks) {
            uint2 b = sB[(ks * 128 + nt) * 32 + lane];
            mma16816(c, A[ks][0], A[ks][1], A[ks][2], A[ks][3], b.x, b.y);
        }
        Zlo[nt * 4] = h2pack(c[0], c[1]);
        Zhi[nt * 4] = h2pack(c[2], c[3]);
    }
}

// ---------------- node term: out = x @ node_W.T (also un-poisons out) ----------------
__global__ void node_kernel(const float* __restrict__ x, const float* __restrict__ nW,
                            float* __restrict__ out, int N) {
    __shared__ float sW[32 * 32];
    int t = threadIdx.x;
    for (int i = t; i < 1024; i += blockDim.x) sW[i] = nW[i];
    __syncthreads();
    int n = blockIdx.x * blockDim.x + t;
    if (n >= N) return;
    float xr[32];
    const float4* xv = (const float4*)(x + (size_t)n * 32);
#pragma unroll
    for (int i = 0; i < 8; ++i) {
        float4 v = xv[i];
        xr[i * 4 + 0] = v.x; xr[i * 4 + 1] = v.y;
        xr[i * 4 + 2] = v.z; xr[i * 4 + 3] = v.w;
    }
    float4* ov = (float4*)(out + (size_t)n * 32);
#pragma unroll
    for (int hq = 0; hq < 8; ++hq) {
        float a0 = 0.f, a1 = 0.f, a2 = 0.f, a3 = 0.f;
#pragma unroll
        for (int d = 0; d < 32; ++d) {
            float xd = xr[d];
            a0 += xd * sW[(hq * 4 + 0) * 32 + d];
            a1 += xd * sW[(hq * 4 + 1) * 32 + d];
            a2 += xd * sW[(hq * 4 + 2) * 32 + d];
            a3 += xd * sW[(hq * 4 + 3) * 32 + d];
        }
        ov[hq] = make_float4(a0, a1, a2, a3);
    }
}

// ---------------- phase 2: warp per node, msgs scatter (pipelined) ----------------
__global__ void __launch_bounds__(256)
msg_kernel(const float* __restrict__ ea, float* __restrict__ out, int N) {
    __shared__ float sea[8][2][32];
    const int lane = threadIdx.x & 31, w = threadIdx.x >> 5;
    const int n = blockIdx.x * 8 + w;
    if (n >= N) return;
    const int beg = g_off[n], end = g_off[n + 1];
    if (beg == end) return;

    // Z row -> registers: lane = h, z[k] = Z[n][h*32+k]
    float z[32];
    {
        const uint4* zp = ((const uint4*)g_Z) + (size_t)n * 128 + lane * 4;
#pragma unroll
        for (int j = 0; j < 4; ++j) {
            uint4 v = zp[j];
            uint32_t p[4] = {v.x, v.y, v.z, v.w};
#pragma unroll
            for (int q = 0; q < 4; ++q) {
                float2 f = __half22float2(*(__half2*)&p[q]);
                z[j * 8 + q * 2 + 0] = f.x;
                z[j * 8 + q * 2 + 1] = f.y;
            }
        }
    }

    // software pipeline: prefetch edge i+1's ea while computing edge i
    int2 sd = g_sorted[beg];
    float v = ea[(size_t)sd.x * 32 + lane];
    int buf = 0;
    sea[w][0][lane] = v;

    for (int i = beg; i < end; ++i) {
        int2 sd_n;
        float v_n;
        if (i + 1 < end) {
            sd_n = g_sorted[i + 1];
            v_n = ea[(size_t)sd_n.x * 32 + lane];
        }
        __syncwarp();
        float acc = 0.f;
        const float* er = sea[w][buf];
#pragma unroll
        for (int k = 0; k < 32; ++k) acc = fmaf(er[k], z[k], acc);
        red_add_f32(out + (size_t)sd.y * 32 + lane, acc);
        if (i + 1 < end) {
            buf ^= 1;
            sea[w][buf][lane] = v_n;
            sd = sd_n;
        }
    }
}

extern "C" void kernel_launch(void* const* d_in, const int* in_sizes, int n_in,
                              void* d_out, int out_size) {
    const float* x      = (const float*)d_in[0];  // [N,32]
    const float* ea     = (const float*)d_in[1];  // [E,32]
    const float* edge_W = (const float*)d_in[2];  // [1024,32]
    const float* node_W = (const float*)d_in[3];  // [32,32]
    const int*   ei     = (const int*)d_in[4];    // [2,E]
    float* out = (float*)d_out;

    const int N = in_sizes[0] / DD;
    const int E = in_sizes[4] / 2;
    const int* src = ei;
    const int* dst = ei + E;
    const int MT = (N + 15) / 16;

    static bool attr_set = false;
    if (!attr_set) {
        cudaFuncSetAttribute(zgemm_kernel,
                             cudaFuncAttributeMaxDynamicSharedMemorySize, ZG_SMEM);
        attr_set = true;
    }

    // sort edges by src
    zero_hist<<<(NB + 255) / 256, 256>>>();
    count_kernel<<<(E + 255) / 256, 256>>>(src, E);
    scan_kernel<<<1, 1024>>>();
    scatter_kernel<<<(E + 255) / 256, 256>>>(src, dst, E);

    // Z = per-node transformed features
    prep_B1<<<32, 256>>>(edge_W);
    zgemm_kernel<<<(MT + 7) / 8, 256, ZG_SMEM>>>(x, N, MT);

    // node term (initializes out), then edge messages
    node_kernel<<<(N + 127) / 128, 128>>>(x, node_W, out, N);
    msg_kernel<<<(N + 7) / 8, 256>>>(ea, out, N);
}